// round 16
// baseline (speedup 1.0000x reference)
#include <cuda_runtime.h>

#define NPX 16384
#define FULL 0xffffffffu

// Scratch: conv output angles + fused gate matrices.
// d_fg4[t*4 .. t*4+3] for t = b*8+w (40 fused CU3 gates):
//   [0] = A row0 (A00, A01)   [1] = A row1 swizzled (A11, A10)
//   [2] = B row0 (B00, B01)   [3] = B row1 swizzled (B11, B10)
// A = ctrl-0 matrix, B = ctrl-1 matrix (next U3 layer fused in).
// d_fg4[160..161] = U3(block0, wire0) normal rows (folded into init state).
__device__ float  d_ang[NPX * 8];
__device__ float4 d_fg4[162];

// ---------------------------------------------------------------------------
__device__ __forceinline__ float2 cmul(float2 a, float2 b) {
    return make_float2(a.x * b.x - a.y * b.y, a.x * b.y + a.y * b.x);
}
__device__ __forceinline__ float2 cadd(float2 a, float2 b) {
    return make_float2(a.x + b.x, a.y + b.y);
}
__device__ __forceinline__ void u3m(const float* p, float2* M) {
    float th = p[0], ph = p[1], la = p[2];
    float s, c;     sincosf(0.5f * th, &s, &c);
    float sl, cl;   sincosf(la, &sl, &cl);
    float sp, cp;   sincosf(ph, &sp, &cp);
    float spl, cpl; sincosf(ph + la, &spl, &cpl);
    M[0] = make_float2(c, 0.0f);
    M[1] = make_float2(-cl * s, -sl * s);
    M[2] = make_float2(cp * s, sp * s);
    M[3] = make_float2(cpl * c, spl * c);
}
__device__ __forceinline__ void mm2(const float2* X, const float2* Y, float2* Z) {
    Z[0] = cadd(cmul(X[0], Y[0]), cmul(X[1], Y[2]));
    Z[1] = cadd(cmul(X[0], Y[1]), cmul(X[1], Y[3]));
    Z[2] = cadd(cmul(X[2], Y[0]), cmul(X[3], Y[2]));
    Z[3] = cadd(cmul(X[2], Y[1]), cmul(X[3], Y[3]));
}

// ---------------------------------------------------------------------------
// Kernel 1: 3x3 SAME conv 16->8ch, smem-staged + fully coalesced.
// One block = 32 contiguous pixels of one row. 4 warps x 4 input channels.
// Last block computes the fused gate matrices (two-phase parallel setup).
// ---------------------------------------------------------------------------
__global__ void __launch_bounds__(128)
conv_kernel(const float* __restrict__ x, const float* __restrict__ cw,
            const float* __restrict__ cb, const float* __restrict__ u3p,
            const float* __restrict__ cu3p) {
    if (blockIdx.x == gridDim.x - 1) {
        // Phase A: 80 threads, one u3 matrix each (4 overlapped sincosf).
        __shared__ float2 sM[80][4];   // [0..39] = u3(b,w), [40..79] = cu3(b,w)
        int t = threadIdx.x;
        if (t < 80) {
            const float* p = (t < 40) ? (u3p + 3 * t) : (cu3p + 3 * (t - 40));
            float2 M[4];
            u3m(p, M);
            sM[t][0] = M[0]; sM[t][1] = M[1]; sM[t][2] = M[2]; sM[t][3] = M[3];
        }
        __syncthreads();
        // Phase B: 40 threads, one fused gate each (pure 2x2 complex algebra).
        if (t < 40) {
            int b = t >> 3, w = t & 7;
            float2 U[4], C[4], B[4];
            if (w < 7) {
                float2* s = sM[b * 8 + w + 1];
                U[0] = s[0]; U[1] = s[1]; U[2] = s[2]; U[3] = s[3];
            } else if (b < 4) {
                float2* s = sM[(b + 1) * 8];
                U[0] = s[0]; U[1] = s[1]; U[2] = s[2]; U[3] = s[3];
            } else {
                U[0] = make_float2(1, 0); U[1] = make_float2(0, 0);
                U[2] = make_float2(0, 0); U[3] = make_float2(1, 0);
            }
            C[0] = sM[40 + t][0]; C[1] = sM[40 + t][1];
            C[2] = sM[40 + t][2]; C[3] = sM[40 + t][3];
            if (w < 7) mm2(C, U, B);   // U3 first, then CU3
            else       mm2(U, C, B);   // CU3(7,0) first, then next-block U3(.,0)
            float4* o = d_fg4 + t * 4;
            o[0] = make_float4(U[0].x, U[0].y, U[1].x, U[1].y);
            o[1] = make_float4(U[3].x, U[3].y, U[2].x, U[2].y);
            o[2] = make_float4(B[0].x, B[0].y, B[1].x, B[1].y);
            o[3] = make_float4(B[3].x, B[3].y, B[2].x, B[2].y);
        }
        if (t == 40) {   // U3(0,0) for init fold, normal rows (from smem)
            d_fg4[160] = make_float4(sM[0][0].x, sM[0][0].y, sM[0][1].x, sM[0][1].y);
            d_fg4[161] = make_float4(sM[0][2].x, sM[0][2].y, sM[0][3].x, sM[0][3].y);
        }
        return;
    }

    // smem: input halo tile + transposed weights + cross-warp partials
    __shared__ __align__(16) float sx[16 * 3 * 36];   // [ci][r][c], c-pad 36
    __shared__ __align__(16) float swt[1152];          // [widx][q]
    __shared__ __align__(16) float sacc[4 * 32 * 8];   // [warp][px][q]
    __shared__ float sb[8];

    int tid = threadIdx.x;
    int p0  = blockIdx.x * 32;                 // 32 contiguous pixels, same row
    int bN  = p0 >> 12, h = (p0 >> 6) & 63, w0 = p0 & 63;

    // transposed weights (one-time)
    for (int i = tid; i < 1152; i += 128) {
        int q = i / 144, widx = i % 144;
        swt[widx * 8 + q] = cw[i];
    }
    if (tid < 8) sb[tid] = cb[tid];

    // Phase 1: coalesced halo load, 16ch x 3rows x 34cols (zero-padded)
    for (int i = tid; i < 16 * 3 * 34; i += 128) {
        int ci = i / 102, rem = i - ci * 102;
        int r = rem / 34,  c = rem - r * 34;
        int hh = h + r - 1, ww = w0 + c - 1;
        float v = 0.0f;
        if (hh >= 0 && hh < 64 && ww >= 0 && ww < 64)
            v = x[((bN * 16 + ci) << 12) + hh * 64 + ww];
        sx[(ci * 3 + r) * 36 + c] = v;
    }
    __syncthreads();

    // Phase 2: warp wp owns channels 4*wp..4*wp+3; lane = pixel
    int wp = tid >> 5, lane = tid & 31;
    float acc[8];
#pragma unroll
    for (int q = 0; q < 8; q++) acc[q] = 0.0f;
#pragma unroll
    for (int cc = 0; cc < 4; cc++) {
        int ci = wp * 4 + cc;
#pragma unroll
        for (int r = 0; r < 3; r++) {
            const float* row = &sx[(ci * 3 + r) * 36];
#pragma unroll
            for (int kw = 0; kw < 3; kw++) {
                float xv = row[lane + kw];                 // conflict-free
                const float4* wrow = (const float4*)&swt[(ci * 9 + r * 3 + kw) * 8];
                float4 wa = wrow[0], wb = wrow[1];         // broadcast
                acc[0] += xv * wa.x; acc[1] += xv * wa.y;
                acc[2] += xv * wa.z; acc[3] += xv * wa.w;
                acc[4] += xv * wb.x; acc[5] += xv * wb.y;
                acc[6] += xv * wb.z; acc[7] += xv * wb.w;
            }
        }
    }
    // write partials
    float4* sa4 = (float4*)&sacc[(wp * 32 + lane) * 8];
    sa4[0] = make_float4(acc[0], acc[1], acc[2], acc[3]);
    sa4[1] = make_float4(acc[4], acc[5], acc[6], acc[7]);
    __syncthreads();

    // Phase 3: 128 threads x 2 outputs: sum 4 warp-partials, add bias, store
    {
        int idx = tid * 2;                 // over 32px * 8q
        int px = idx >> 3, q = idx & 7;
        const float2* s0 = (const float2*)&sacc[(0 * 32 + px) * 8 + q];
        const float2* s1 = (const float2*)&sacc[(1 * 32 + px) * 8 + q];
        const float2* s2 = (const float2*)&sacc[(2 * 32 + px) * 8 + q];
        const float2* s3 = (const float2*)&sacc[(3 * 32 + px) * 8 + q];
        float2 a = *s0, b = *s1, c = *s2, d = *s3;
        float r0 = a.x + b.x + c.x + d.x + sb[q];
        float r1 = a.y + b.y + c.y + d.y + sb[q + 1];
        *(float2*)&d_ang[(p0 + px) * 8 + q] = make_float2(r0, r1);
    }
}

// ---------------------------------------------------------------------------
// Register-resident state: index i = lane + 32*k. Lane bits 0..4 = wires 7..3,
// k bits 0,1,2 = wires 2,1,0.
// ---------------------------------------------------------------------------
__device__ __forceinline__ void cpair(float& a0r, float& a0i, float& a1r, float& a1i,
                                      float2 u00, float2 u01, float2 u10, float2 u11) {
    float n0r = u00.x * a0r - u00.y * a0i + u01.x * a1r - u01.y * a1i;
    float n0i = u00.x * a0i + u00.y * a0r + u01.x * a1i + u01.y * a1r;
    float n1r = u10.x * a0r - u10.y * a0i + u11.x * a1r - u11.y * a1i;
    float n1i = u10.x * a0i + u10.y * a0r + u11.x * a1i + u11.y * a1r;
    a0r = n0r; a0i = n0i; a1r = n1r; a1i = n1i;
}

template <int Q>
__device__ __forceinline__ void lane_body(float* ar, float* ai, int k, float2 d0, float2 d1) {
    float orr = __shfl_xor_sync(FULL, ar[k], 1 << Q);
    float oii = __shfl_xor_sync(FULL, ai[k], 1 << Q);
    float nr = d0.x * ar[k] - d0.y * ai[k] + d1.x * orr - d1.y * oii;
    float ni = d0.x * ai[k] + d0.y * ar[k] + d1.x * oii + d1.y * orr;
    ar[k] = nr; ai[k] = ni;
}

// ---- fused CU3 gates (A = ctrl0, B = ctrl1, swizzled rows in g[0..3]) ----
template <int TB, int CB>
__device__ __forceinline__ void fgate_rr(float* ar, float* ai, const float4* g) {
    float4 a0 = g[0], a1 = g[1], b0 = g[2], b1 = g[3];
#pragma unroll
    for (int k0 = 0; k0 < 8; k0++)
        if (!(k0 & (1 << TB))) {
            float4 r0 = (k0 & (1 << CB)) ? b0 : a0;
            float4 r1 = (k0 & (1 << CB)) ? b1 : a1;
            int k1 = k0 | (1 << TB);
            cpair(ar[k0], ai[k0], ar[k1], ai[k1],
                  make_float2(r0.x, r0.y), make_float2(r0.z, r0.w),
                  make_float2(r1.z, r1.w), make_float2(r1.x, r1.y));
        }
}

__device__ __forceinline__ void fgate_lk(float* ar, float* ai, int lane, const float4* g) {
    int tb = (lane >> 4) & 1;
    float4 rA = g[tb];
    float4 rB = g[2 + tb];
    float2 d0A = make_float2(rA.x, rA.y), d1A = make_float2(rA.z, rA.w);
    float2 d0B = make_float2(rB.x, rB.y), d1B = make_float2(rB.z, rB.w);
#pragma unroll
    for (int k = 0; k < 8; k++)
        lane_body<4>(ar, ai, k, (k & 1) ? d0B : d0A, (k & 1) ? d1B : d1A);
}

template <int Q, int CQ>
__device__ __forceinline__ void fgate_ll(float* ar, float* ai, int lane, const float4* g) {
    int idx = (((lane >> CQ) & 1) << 1) | ((lane >> Q) & 1);
    float4 r = g[idx];
    float2 d0 = make_float2(r.x, r.y), d1 = make_float2(r.z, r.w);
#pragma unroll
    for (int k = 0; k < 8; k++) lane_body<Q>(ar, ai, k, d0, d1);
}

__device__ __forceinline__ void fgate_rl(float* ar, float* ai, int lane, const float4* g) {
    const float4* M = g + ((lane & 1) << 1);
    float4 r0 = M[0], r1 = M[1];
    float2 u00 = make_float2(r0.x, r0.y), u01 = make_float2(r0.z, r0.w);
    float2 u11 = make_float2(r1.x, r1.y), u10 = make_float2(r1.z, r1.w);
#pragma unroll
    for (int k0 = 0; k0 < 4; k0++)
        cpair(ar[k0], ai[k0], ar[k0 + 4], ai[k0 + 4], u00, u01, u10, u11);
}

// full-warp butterfly sum (all lanes get result)
__device__ __forceinline__ float wsum(float x) {
#pragma unroll
    for (int o = 16; o; o >>= 1) x += __shfl_xor_sync(FULL, x, o);
    return x;
}

// paired warp sum: reduces u and v together in 6 SHFL (vs 10).
__device__ __forceinline__ void psum2(float u, float v, int lane, float& U, float& V) {
    float t = __shfl_xor_sync(FULL, (lane & 1) ? u : v, 1);
    float s = ((lane & 1) ? v : u) + t;
#pragma unroll
    for (int o = 2; o <= 16; o <<= 1) s += __shfl_xor_sync(FULL, s, o);
    float w = __shfl_xor_sync(FULL, s, 1);
    U = (lane & 1) ? w : s;
    V = (lane & 1) ? s : w;
}

// lane-wire <X>/my partials for lane bit Q
template <int Q>
__device__ __forceinline__ void xy_lane(const float* ar, const float* ai, int lane,
                                        float& uo, float& vo) {
    float uu = 0.0f, vv = 0.0f;
#pragma unroll
    for (int k = 0; k < 8; k++) {
        float orr = __shfl_xor_sync(FULL, ar[k], 1 << Q);
        float oii = __shfl_xor_sync(FULL, ai[k], 1 << Q);
        uu += ar[k] * orr + ai[k] * oii;
        vv += ai[k] * orr - ar[k] * oii;
    }
    uo = uu;
    vo = (lane & (1 << Q)) ? -vv : vv;
}

// ---------------------------------------------------------------------------
// Kernel 2: one warp per pixel. Main circuit + direct Pauli measurement.
// ---------------------------------------------------------------------------
__global__ void __launch_bounds__(128)
sim_kernel(const float* __restrict__ fc_w, const float* __restrict__ fc_b,
           float* __restrict__ out) {
    __shared__ float4 sg[162];
    int t = threadIdx.x, wp = t >> 5, lane = t & 31;
    int pix = blockIdx.x * 4 + wp;

    for (int i = t; i < 162; i += 128) sg[i] = d_fg4[i];

    float mys = 0.0f, myc = 1.0f;
    if (lane < 8) {
        float a = d_ang[pix * 8 + lane];
        sincosf(0.5f * a, &mys, &myc);
    }
    float cw[8], sw_[8];
#pragma unroll
    for (int w = 0; w < 8; w++) {
        cw[w]  = __shfl_sync(FULL, myc, w);
        sw_[w] = __shfl_sync(FULL, mys, w);
    }
    float lf = 1.0f;
#pragma unroll
    for (int q = 0; q < 5; q++) {          // lane bits 0..4 = wires 7..3
        int w = 7 - q;
        lf *= ((lane >> q) & 1) ? sw_[w] : cw[w];
    }
    __syncthreads();   // sg ready

    // fold U3(block0, wire0) into the wire-0 initial vector
    float4 M0 = sg[160], M1 = sg[161];
    float v0r = M0.x * cw[0] + M0.z * sw_[0];
    float v0i = M0.y * cw[0] + M0.w * sw_[0];
    float v1r = M1.x * cw[0] + M1.z * sw_[0];
    float v1i = M1.y * cw[0] + M1.w * sw_[0];

    float ar[8], ai[8];
#pragma unroll
    for (int k = 0; k < 8; k++) {
        float rp = lf * ((k & 1) ? sw_[2] : cw[2]) * ((k & 2) ? sw_[1] : cw[1]);
        ar[k] = rp * ((k & 4) ? v1r : v0r);
        ai[k] = rp * ((k & 4) ? v1i : v0i);
    }

    // 5 blocks of 8 fused CU3 gates (U3 layers absorbed)
#pragma unroll 1
    for (int b = 0; b < 5; b++) {
        const float4* gb = sg + b * 32;
        fgate_rr<1, 2>(ar, ai, gb + 0);         // c=w0(kb2), t=w1(kb1)
        fgate_rr<0, 1>(ar, ai, gb + 4);         // c=kb1, t=kb0
        fgate_lk(ar, ai, lane, gb + 8);         // c=kb0, t=lane4
        fgate_ll<3, 4>(ar, ai, lane, gb + 12);
        fgate_ll<2, 3>(ar, ai, lane, gb + 16);
        fgate_ll<1, 2>(ar, ai, lane, gb + 20);
        fgate_ll<0, 1>(ar, ai, lane, gb + 24);
        fgate_rl(ar, ai, lane, gb + 28);        // c=lane0, t=kb2
    }

    // ---- direct Pauli measurement (no basis-change layers) ----
    float p0 = ar[0]*ar[0] + ai[0]*ai[0], p1 = ar[1]*ar[1] + ai[1]*ai[1];
    float p2 = ar[2]*ar[2] + ai[2]*ai[2], p3 = ar[3]*ar[3] + ai[3]*ai[3];
    float p4 = ar[4]*ar[4] + ai[4]*ai[4], p5 = ar[5]*ar[5] + ai[5]*ai[5];
    float p6 = ar[6]*ar[6] + ai[6]*ai[6], p7 = ar[7]*ar[7] + ai[7]*ai[7];
    float sa = p0 + p1, sb2 = p2 + p3, sc = p4 + p5, sd = p6 + p7;
    float se = p0 + p2, sf = p4 + p6, sh = p1 + p3, si = p5 + p7;
    float tt = (sa + sb2) + (sc + sd);
    float z0 = (sa + sb2) - (sc + sd);      // wire0 (kb2)
    float z1 = (sa + sc) - (sb2 + sd);      // wire1 (kb1)
    float z2 = (se + sf) - (sh + si);       // wire2 (kb0)

    // Walsh-Hadamard of tt over lane bits: W(2^q) lands on lane 2^q
    float wt = tt;
#pragma unroll
    for (int o = 1; o <= 16; o <<= 1) {
        float r = __shfl_xor_sync(FULL, wt, o);
        wt = (lane & o) ? (r - wt) : (wt + r);
    }

    // reg-wire <X>/my partials (a0 = lower index); mx = 2*sum, my = 2*sum
    float u0 = 0, v0 = 0, u1 = 0, v1 = 0, u2 = 0, v2 = 0;
#pragma unroll
    for (int k = 0; k < 4; k++) {           // wire0: (k, k+4)
        u0 += ar[k] * ar[k+4] + ai[k] * ai[k+4];
        v0 += ai[k] * ar[k+4] - ar[k] * ai[k+4];
    }
#pragma unroll
    for (int k = 0; k < 8; k++)             // wire1: (k, k+2), bit1 clear
        if (!(k & 2)) {
            u1 += ar[k] * ar[k+2] + ai[k] * ai[k+2];
            v1 += ai[k] * ar[k+2] - ar[k] * ai[k+2];
        }
#pragma unroll
    for (int k = 0; k < 8; k += 2) {        // wire2: (k, k+1)
        u2 += ar[k] * ar[k+1] + ai[k] * ai[k+1];
        v2 += ai[k] * ar[k+1] - ar[k] * ai[k+1];
    }

    // lane-wire partials (wire 7-q for lane bit q)
    float ulq0, vlq0, ulq1, vlq1, ulq2, vlq2, ulq3, vlq3, ulq4, vlq4;
    xy_lane<0>(ar, ai, lane, ulq0, vlq0);   // wire7
    xy_lane<1>(ar, ai, lane, ulq1, vlq1);   // wire6
    xy_lane<2>(ar, ai, lane, ulq2, vlq2);   // wire5
    xy_lane<3>(ar, ai, lane, ulq3, vlq3);   // wire4
    xy_lane<4>(ar, ai, lane, ulq4, vlq4);   // wire3

    // paired reductions (results warp-uniform)
    float mz0, mz1;           psum2(z0, z1, lane, mz0, mz1);
    float mz2 = wsum(z2);
    float mx0, my0;           psum2(u0, v0, lane, mx0, my0);
    float mx1, my1;           psum2(u1, v1, lane, mx1, my1);
    float mx2, my2;           psum2(u2, v2, lane, mx2, my2);
    mx0 *= 2.0f; mx1 *= 2.0f; mx2 *= 2.0f;
    my0 *= 2.0f; my1 *= 2.0f; my2 *= 2.0f;
    float mx3, my3;           psum2(ulq4, vlq4, lane, mx3, my3);
    float mx4, my4;           psum2(ulq3, vlq3, lane, mx4, my4);
    float mx5, my5;           psum2(ulq2, vlq2, lane, mx5, my5);
    float mx6, my6;           psum2(ulq1, vlq1, lane, mx6, my6);
    float mx7, my7;           psum2(ulq0, vlq0, lane, mx7, my7);
    // mz for lane wires from Walsh lanes 16,8,4,2,1 (wires 3..7)
    float mz3 = __shfl_sync(FULL, wt, 16);
    float mz4 = __shfl_sync(FULL, wt, 8);
    float mz5 = __shfl_sync(FULL, wt, 4);
    float mz6 = __shfl_sync(FULL, wt, 2);
    float mz7 = __shfl_sync(FULL, wt, 1);

    // fused FC: one lane per output channel; fc_w row = 24 floats = 6 float4
    const float4* fw4 = (const float4*)fc_w + lane * 6;
    float4 w0 = __ldg(fw4 + 0), w1 = __ldg(fw4 + 1), w2 = __ldg(fw4 + 2);
    float4 w3 = __ldg(fw4 + 3), w4 = __ldg(fw4 + 4), w5 = __ldg(fw4 + 5);
    float o = __ldg(&fc_b[lane]);
    o += w0.x * mz0 + w0.y * mz1 + w0.z * mz2 + w0.w * mz3;
    o += w1.x * mz4 + w1.y * mz5 + w1.z * mz6 + w1.w * mz7;
    o += w2.x * mx0 + w2.y * mx1 + w2.z * mx2 + w2.w * mx3;
    o += w3.x * mx4 + w3.y * mx5 + w3.z * mx6 + w3.w * mx7;
    o += w4.x * my0 + w4.y * my1 + w4.z * my2 + w4.w * my3;
    o += w5.x * my4 + w5.y * my5 + w5.z * my6 + w5.w * my7;

    int bN = pix >> 12, hw = pix & 4095;
    out[(bN * 32 + lane) * 4096 + hw] = o;
}

// ---------------------------------------------------------------------------
extern "C" void kernel_launch(void* const* d_in, const int* in_sizes, int n_in,
                              void* d_out, int out_size) {
    const float* x      = (const float*)d_in[0];
    const float* conv_w = (const float*)d_in[1];
    const float* conv_b = (const float*)d_in[2];
    const float* u3p    = (const float*)d_in[3];
    const float* cu3p   = (const float*)d_in[4];
    const float* fc_w   = (const float*)d_in[5];
    const float* fc_b   = (const float*)d_in[6];
    float* out = (float*)d_out;

    conv_kernel<<<NPX / 32 + 1, 128>>>(x, conv_w, conv_b, u3p, cu3p);
    sim_kernel<<<NPX / 4, 128>>>(fc_w, fc_b, out);
}

// round 17
// speedup vs baseline: 1.5969x; 1.5969x over previous
#include <cuda_runtime.h>

#define NPX 16384
#define FULL 0xffffffffu

// Scratch: conv output angles + fused gate matrices.
// d_fg4[t*4 .. t*4+3] for t = b*8+w (40 fused CU3 gates):
//   [0] = A row0 (A00, A01)   [1] = A row1 swizzled (A11, A10)
//   [2] = B row0 (B00, B01)   [3] = B row1 swizzled (B11, B10)
// A = ctrl-0 matrix, B = ctrl-1 matrix (next U3 layer fused in).
// d_fg4[160..161] = U3(block0, wire0) normal rows (folded into init state).
__device__ float  d_ang[NPX * 8];
__device__ float4 d_fg4[162];

// ---------------------------------------------------------------------------
__device__ __forceinline__ float2 cmul(float2 a, float2 b) {
    return make_float2(a.x * b.x - a.y * b.y, a.x * b.y + a.y * b.x);
}
__device__ __forceinline__ float2 cadd(float2 a, float2 b) {
    return make_float2(a.x + b.x, a.y + b.y);
}
__device__ __forceinline__ void u3m(const float* p, float2* M) {
    float th = p[0], ph = p[1], la = p[2];
    float s, c;     sincosf(0.5f * th, &s, &c);
    float sl, cl;   sincosf(la, &sl, &cl);
    float sp, cp;   sincosf(ph, &sp, &cp);
    float spl, cpl; sincosf(ph + la, &spl, &cpl);
    M[0] = make_float2(c, 0.0f);
    M[1] = make_float2(-cl * s, -sl * s);
    M[2] = make_float2(cp * s, sp * s);
    M[3] = make_float2(cpl * c, spl * c);
}
__device__ __forceinline__ void mm2(const float2* X, const float2* Y, float2* Z) {
    Z[0] = cadd(cmul(X[0], Y[0]), cmul(X[1], Y[2]));
    Z[1] = cadd(cmul(X[0], Y[1]), cmul(X[1], Y[3]));
    Z[2] = cadd(cmul(X[2], Y[0]), cmul(X[3], Y[2]));
    Z[3] = cadd(cmul(X[2], Y[1]), cmul(X[3], Y[3]));
}

// ---------------------------------------------------------------------------
// Kernel 1: 3x3 SAME conv 16->8ch, smem-staged + fully coalesced.
// One block = 32 contiguous pixels of one row. 4 warps x 4 input channels.
// Last block computes the fused gate matrices (two-phase parallel setup).
// ---------------------------------------------------------------------------
__global__ void __launch_bounds__(128)
conv_kernel(const float* __restrict__ x, const float* __restrict__ cw,
            const float* __restrict__ cb, const float* __restrict__ u3p,
            const float* __restrict__ cu3p) {
    if (blockIdx.x == gridDim.x - 1) {
        // Phase A: 80 threads, one u3 matrix each (4 overlapped sincosf).
        __shared__ float2 sM[80][4];   // [0..39] = u3(b,w), [40..79] = cu3(b,w)
        int t = threadIdx.x;
        if (t < 80) {
            const float* p = (t < 40) ? (u3p + 3 * t) : (cu3p + 3 * (t - 40));
            float2 M[4];
            u3m(p, M);
            sM[t][0] = M[0]; sM[t][1] = M[1]; sM[t][2] = M[2]; sM[t][3] = M[3];
        }
        __syncthreads();
        // Phase B: 40 threads, one fused gate each (pure 2x2 complex algebra).
        if (t < 40) {
            int b = t >> 3, w = t & 7;
            float2 U[4], C[4], B[4];
            if (w < 7) {
                float2* s = sM[b * 8 + w + 1];
                U[0] = s[0]; U[1] = s[1]; U[2] = s[2]; U[3] = s[3];
            } else if (b < 4) {
                float2* s = sM[(b + 1) * 8];
                U[0] = s[0]; U[1] = s[1]; U[2] = s[2]; U[3] = s[3];
            } else {
                U[0] = make_float2(1, 0); U[1] = make_float2(0, 0);
                U[2] = make_float2(0, 0); U[3] = make_float2(1, 0);
            }
            C[0] = sM[40 + t][0]; C[1] = sM[40 + t][1];
            C[2] = sM[40 + t][2]; C[3] = sM[40 + t][3];
            if (w < 7) mm2(C, U, B);   // U3 first, then CU3
            else       mm2(U, C, B);   // CU3(7,0) first, then next-block U3(.,0)
            float4* o = d_fg4 + t * 4;
            o[0] = make_float4(U[0].x, U[0].y, U[1].x, U[1].y);
            o[1] = make_float4(U[3].x, U[3].y, U[2].x, U[2].y);
            o[2] = make_float4(B[0].x, B[0].y, B[1].x, B[1].y);
            o[3] = make_float4(B[3].x, B[3].y, B[2].x, B[2].y);
        }
        if (t == 40) {   // U3(0,0) for init fold, normal rows (from smem)
            d_fg4[160] = make_float4(sM[0][0].x, sM[0][0].y, sM[0][1].x, sM[0][1].y);
            d_fg4[161] = make_float4(sM[0][2].x, sM[0][2].y, sM[0][3].x, sM[0][3].y);
        }
        return;
    }

    // smem: input halo tile + transposed weights + cross-warp partials
    __shared__ __align__(16) float sx[16 * 3 * 36];   // [ci][r][c], c-pad 36
    __shared__ __align__(16) float swt[1152];          // [widx][q]
    __shared__ __align__(16) float sacc[4 * 32 * 8];   // [warp][px][q]
    __shared__ float sb[8];

    int tid = threadIdx.x;
    int p0  = blockIdx.x * 32;                 // 32 contiguous pixels, same row
    int bN  = p0 >> 12, h = (p0 >> 6) & 63, w0 = p0 & 63;

    // transposed weights (one-time)
    for (int i = tid; i < 1152; i += 128) {
        int q = i / 144, widx = i % 144;
        swt[widx * 8 + q] = cw[i];
    }
    if (tid < 8) sb[tid] = cb[tid];

    // Phase 1: coalesced halo load, 16ch x 3rows x 34cols (zero-padded)
    for (int i = tid; i < 16 * 3 * 34; i += 128) {
        int ci = i / 102, rem = i - ci * 102;
        int r = rem / 34,  c = rem - r * 34;
        int hh = h + r - 1, ww = w0 + c - 1;
        float v = 0.0f;
        if (hh >= 0 && hh < 64 && ww >= 0 && ww < 64)
            v = x[((bN * 16 + ci) << 12) + hh * 64 + ww];
        sx[(ci * 3 + r) * 36 + c] = v;
    }
    __syncthreads();

    // Phase 2: warp wp owns channels 4*wp..4*wp+3; lane = pixel
    int wp = tid >> 5, lane = tid & 31;
    float acc[8];
#pragma unroll
    for (int q = 0; q < 8; q++) acc[q] = 0.0f;
#pragma unroll
    for (int cc = 0; cc < 4; cc++) {
        int ci = wp * 4 + cc;
#pragma unroll
        for (int r = 0; r < 3; r++) {
            const float* row = &sx[(ci * 3 + r) * 36];
#pragma unroll
            for (int kw = 0; kw < 3; kw++) {
                float xv = row[lane + kw];                 // conflict-free
                const float4* wrow = (const float4*)&swt[(ci * 9 + r * 3 + kw) * 8];
                float4 wa = wrow[0], wb = wrow[1];         // broadcast
                acc[0] += xv * wa.x; acc[1] += xv * wa.y;
                acc[2] += xv * wa.z; acc[3] += xv * wa.w;
                acc[4] += xv * wb.x; acc[5] += xv * wb.y;
                acc[6] += xv * wb.z; acc[7] += xv * wb.w;
            }
        }
    }
    // write partials
    float4* sa4 = (float4*)&sacc[(wp * 32 + lane) * 8];
    sa4[0] = make_float4(acc[0], acc[1], acc[2], acc[3]);
    sa4[1] = make_float4(acc[4], acc[5], acc[6], acc[7]);
    __syncthreads();

    // Phase 3: 128 threads x 2 outputs: sum 4 warp-partials, add bias, store
    {
        int idx = tid * 2;                 // over 32px * 8q
        int px = idx >> 3, q = idx & 7;
        const float2* s0 = (const float2*)&sacc[(0 * 32 + px) * 8 + q];
        const float2* s1 = (const float2*)&sacc[(1 * 32 + px) * 8 + q];
        const float2* s2 = (const float2*)&sacc[(2 * 32 + px) * 8 + q];
        const float2* s3 = (const float2*)&sacc[(3 * 32 + px) * 8 + q];
        float2 a = *s0, b = *s1, c = *s2, d = *s3;
        float r0 = a.x + b.x + c.x + d.x + sb[q];
        float r1 = a.y + b.y + c.y + d.y + sb[q + 1];
        *(float2*)&d_ang[(p0 + px) * 8 + q] = make_float2(r0, r1);
    }
}

// ---------------------------------------------------------------------------
// Register-resident state: index i = lane + 32*k. Lane bits 0..4 = wires 7..3,
// k bits 0,1,2 = wires 2,1,0.
// ---------------------------------------------------------------------------
__device__ __forceinline__ void cpair(float& a0r, float& a0i, float& a1r, float& a1i,
                                      float2 u00, float2 u01, float2 u10, float2 u11) {
    float n0r = u00.x * a0r - u00.y * a0i + u01.x * a1r - u01.y * a1i;
    float n0i = u00.x * a0i + u00.y * a0r + u01.x * a1i + u01.y * a1r;
    float n1r = u10.x * a0r - u10.y * a0i + u11.x * a1r - u11.y * a1i;
    float n1i = u10.x * a0i + u10.y * a0r + u11.x * a1i + u11.y * a1r;
    a0r = n0r; a0i = n0i; a1r = n1r; a1i = n1i;
}

template <int Q>
__device__ __forceinline__ void lane_body(float* ar, float* ai, int k, float2 d0, float2 d1) {
    float orr = __shfl_xor_sync(FULL, ar[k], 1 << Q);
    float oii = __shfl_xor_sync(FULL, ai[k], 1 << Q);
    float nr = d0.x * ar[k] - d0.y * ai[k] + d1.x * orr - d1.y * oii;
    float ni = d0.x * ai[k] + d0.y * ar[k] + d1.x * oii + d1.y * orr;
    ar[k] = nr; ai[k] = ni;
}

// ---- fused CU3 gates (A = ctrl0, B = ctrl1, swizzled rows in g[0..3]) ----
template <int TB, int CB>
__device__ __forceinline__ void fgate_rr(float* ar, float* ai, const float4* g) {
    float4 a0 = g[0], a1 = g[1], b0 = g[2], b1 = g[3];
#pragma unroll
    for (int k0 = 0; k0 < 8; k0++)
        if (!(k0 & (1 << TB))) {
            float4 r0 = (k0 & (1 << CB)) ? b0 : a0;
            float4 r1 = (k0 & (1 << CB)) ? b1 : a1;
            int k1 = k0 | (1 << TB);
            cpair(ar[k0], ai[k0], ar[k1], ai[k1],
                  make_float2(r0.x, r0.y), make_float2(r0.z, r0.w),
                  make_float2(r1.z, r1.w), make_float2(r1.x, r1.y));
        }
}

__device__ __forceinline__ void fgate_lk(float* ar, float* ai, int lane, const float4* g) {
    int tb = (lane >> 4) & 1;
    float4 rA = g[tb];
    float4 rB = g[2 + tb];
    float2 d0A = make_float2(rA.x, rA.y), d1A = make_float2(rA.z, rA.w);
    float2 d0B = make_float2(rB.x, rB.y), d1B = make_float2(rB.z, rB.w);
#pragma unroll
    for (int k = 0; k < 8; k++)
        lane_body<4>(ar, ai, k, (k & 1) ? d0B : d0A, (k & 1) ? d1B : d1A);
}

template <int Q, int CQ>
__device__ __forceinline__ void fgate_ll(float* ar, float* ai, int lane, const float4* g) {
    int idx = (((lane >> CQ) & 1) << 1) | ((lane >> Q) & 1);
    float4 r = g[idx];
    float2 d0 = make_float2(r.x, r.y), d1 = make_float2(r.z, r.w);
#pragma unroll
    for (int k = 0; k < 8; k++) lane_body<Q>(ar, ai, k, d0, d1);
}

__device__ __forceinline__ void fgate_rl(float* ar, float* ai, int lane, const float4* g) {
    const float4* M = g + ((lane & 1) << 1);
    float4 r0 = M[0], r1 = M[1];
    float2 u00 = make_float2(r0.x, r0.y), u01 = make_float2(r0.z, r0.w);
    float2 u11 = make_float2(r1.x, r1.y), u10 = make_float2(r1.z, r1.w);
#pragma unroll
    for (int k0 = 0; k0 < 4; k0++)
        cpair(ar[k0], ai[k0], ar[k0 + 4], ai[k0 + 4], u00, u01, u10, u11);
}

// full-warp butterfly sum (all lanes get result)
__device__ __forceinline__ float wsum(float x) {
#pragma unroll
    for (int o = 16; o; o >>= 1) x += __shfl_xor_sync(FULL, x, o);
    return x;
}

// paired warp sum: reduces u and v together in 6 SHFL (vs 10).
__device__ __forceinline__ void psum2(float u, float v, int lane, float& U, float& V) {
    float t = __shfl_xor_sync(FULL, (lane & 1) ? u : v, 1);
    float s = ((lane & 1) ? v : u) + t;
#pragma unroll
    for (int o = 2; o <= 16; o <<= 1) s += __shfl_xor_sync(FULL, s, o);
    float w = __shfl_xor_sync(FULL, s, 1);
    U = (lane & 1) ? w : s;
    V = (lane & 1) ? s : w;
}

// lane-wire <X>/my partials for lane bit Q
template <int Q>
__device__ __forceinline__ void xy_lane(const float* ar, const float* ai, int lane,
                                        float& uo, float& vo) {
    float uu = 0.0f, vv = 0.0f;
#pragma unroll
    for (int k = 0; k < 8; k++) {
        float orr = __shfl_xor_sync(FULL, ar[k], 1 << Q);
        float oii = __shfl_xor_sync(FULL, ai[k], 1 << Q);
        uu += ar[k] * orr + ai[k] * oii;
        vv += ai[k] * orr - ar[k] * oii;
    }
    uo = uu;
    vo = (lane & (1 << Q)) ? -vv : vv;
}

// ---------------------------------------------------------------------------
// Kernel 2: one warp per pixel. Main circuit + direct Pauli measurement.
// ---------------------------------------------------------------------------
__global__ void __launch_bounds__(128)
sim_kernel(const float* __restrict__ fc_w, const float* __restrict__ fc_b,
           float* __restrict__ out) {
    __shared__ float4 sg[162];
    int t = threadIdx.x, wp = t >> 5, lane = t & 31;
    int pix = blockIdx.x * 4 + wp;

    for (int i = t; i < 162; i += 128) sg[i] = d_fg4[i];

    float mys = 0.0f, myc = 1.0f;
    if (lane < 8) {
        float a = d_ang[pix * 8 + lane];
        sincosf(0.5f * a, &mys, &myc);
    }
    float cw[8], sw_[8];
#pragma unroll
    for (int w = 0; w < 8; w++) {
        cw[w]  = __shfl_sync(FULL, myc, w);
        sw_[w] = __shfl_sync(FULL, mys, w);
    }
    float lf = 1.0f;
#pragma unroll
    for (int q = 0; q < 5; q++) {          // lane bits 0..4 = wires 7..3
        int w = 7 - q;
        lf *= ((lane >> q) & 1) ? sw_[w] : cw[w];
    }
    __syncthreads();   // sg ready

    // fold U3(block0, wire0) into the wire-0 initial vector
    float4 M0 = sg[160], M1 = sg[161];
    float v0r = M0.x * cw[0] + M0.z * sw_[0];
    float v0i = M0.y * cw[0] + M0.w * sw_[0];
    float v1r = M1.x * cw[0] + M1.z * sw_[0];
    float v1i = M1.y * cw[0] + M1.w * sw_[0];

    float ar[8], ai[8];
#pragma unroll
    for (int k = 0; k < 8; k++) {
        float rp = lf * ((k & 1) ? sw_[2] : cw[2]) * ((k & 2) ? sw_[1] : cw[1]);
        ar[k] = rp * ((k & 4) ? v1r : v0r);
        ai[k] = rp * ((k & 4) ? v1i : v0i);
    }

    // 5 blocks of 8 fused CU3 gates (U3 layers absorbed)
#pragma unroll 1
    for (int b = 0; b < 5; b++) {
        const float4* gb = sg + b * 32;
        fgate_rr<1, 2>(ar, ai, gb + 0);         // c=w0(kb2), t=w1(kb1)
        fgate_rr<0, 1>(ar, ai, gb + 4);         // c=kb1, t=kb0
        fgate_lk(ar, ai, lane, gb + 8);         // c=kb0, t=lane4
        fgate_ll<3, 4>(ar, ai, lane, gb + 12);
        fgate_ll<2, 3>(ar, ai, lane, gb + 16);
        fgate_ll<1, 2>(ar, ai, lane, gb + 20);
        fgate_ll<0, 1>(ar, ai, lane, gb + 24);
        fgate_rl(ar, ai, lane, gb + 28);        // c=lane0, t=kb2
    }

    // ---- direct Pauli measurement (no basis-change layers) ----
    float p0 = ar[0]*ar[0] + ai[0]*ai[0], p1 = ar[1]*ar[1] + ai[1]*ai[1];
    float p2 = ar[2]*ar[2] + ai[2]*ai[2], p3 = ar[3]*ar[3] + ai[3]*ai[3];
    float p4 = ar[4]*ar[4] + ai[4]*ai[4], p5 = ar[5]*ar[5] + ai[5]*ai[5];
    float p6 = ar[6]*ar[6] + ai[6]*ai[6], p7 = ar[7]*ar[7] + ai[7]*ai[7];
    float sa = p0 + p1, sb2 = p2 + p3, sc = p4 + p5, sd = p6 + p7;
    float se = p0 + p2, sf = p4 + p6, sh = p1 + p3, si = p5 + p7;
    float tt = (sa + sb2) + (sc + sd);
    float z0 = (sa + sb2) - (sc + sd);      // wire0 (kb2)
    float z1 = (sa + sc) - (sb2 + sd);      // wire1 (kb1)
    float z2 = (se + sf) - (sh + si);       // wire2 (kb0)

    // Walsh-Hadamard of tt over lane bits: W(2^q) lands on lane 2^q
    float wt = tt;
#pragma unroll
    for (int o = 1; o <= 16; o <<= 1) {
        float r = __shfl_xor_sync(FULL, wt, o);
        wt = (lane & o) ? (r - wt) : (wt + r);
    }

    // reg-wire <X>/my partials (a0 = lower index); mx = 2*sum, my = 2*sum
    float u0 = 0, v0 = 0, u1 = 0, v1 = 0, u2 = 0, v2 = 0;
#pragma unroll
    for (int k = 0; k < 4; k++) {           // wire0: (k, k+4)
        u0 += ar[k] * ar[k+4] + ai[k] * ai[k+4];
        v0 += ai[k] * ar[k+4] - ar[k] * ai[k+4];
    }
#pragma unroll
    for (int k = 0; k < 8; k++)             // wire1: (k, k+2), bit1 clear
        if (!(k & 2)) {
            u1 += ar[k] * ar[k+2] + ai[k] * ai[k+2];
            v1 += ai[k] * ar[k+2] - ar[k] * ai[k+2];
        }
#pragma unroll
    for (int k = 0; k < 8; k += 2) {        // wire2: (k, k+1)
        u2 += ar[k] * ar[k+1] + ai[k] * ai[k+1];
        v2 += ai[k] * ar[k+1] - ar[k] * ai[k+1];
    }

    // lane-wire partials (wire 7-q for lane bit q)
    float ulq0, vlq0, ulq1, vlq1, ulq2, vlq2, ulq3, vlq3, ulq4, vlq4;
    xy_lane<0>(ar, ai, lane, ulq0, vlq0);   // wire7
    xy_lane<1>(ar, ai, lane, ulq1, vlq1);   // wire6
    xy_lane<2>(ar, ai, lane, ulq2, vlq2);   // wire5
    xy_lane<3>(ar, ai, lane, ulq3, vlq3);   // wire4
    xy_lane<4>(ar, ai, lane, ulq4, vlq4);   // wire3

    // paired reductions (results warp-uniform)
    float mz0, mz1;           psum2(z0, z1, lane, mz0, mz1);
    float mz2 = wsum(z2);
    float mx0, my0;           psum2(u0, v0, lane, mx0, my0);
    float mx1, my1;           psum2(u1, v1, lane, mx1, my1);
    float mx2, my2;           psum2(u2, v2, lane, mx2, my2);
    mx0 *= 2.0f; mx1 *= 2.0f; mx2 *= 2.0f;
    my0 *= 2.0f; my1 *= 2.0f; my2 *= 2.0f;
    float mx3, my3;           psum2(ulq4, vlq4, lane, mx3, my3);
    float mx4, my4;           psum2(ulq3, vlq3, lane, mx4, my4);
    float mx5, my5;           psum2(ulq2, vlq2, lane, mx5, my5);
    float mx6, my6;           psum2(ulq1, vlq1, lane, mx6, my6);
    float mx7, my7;           psum2(ulq0, vlq0, lane, mx7, my7);
    // mz for lane wires from Walsh lanes 16,8,4,2,1 (wires 3..7)
    float mz3 = __shfl_sync(FULL, wt, 16);
    float mz4 = __shfl_sync(FULL, wt, 8);
    float mz5 = __shfl_sync(FULL, wt, 4);
    float mz6 = __shfl_sync(FULL, wt, 2);
    float mz7 = __shfl_sync(FULL, wt, 1);

    // fused FC: one lane per output channel; fc_w row = 24 floats = 6 float4
    const float4* fw4 = (const float4*)fc_w + lane * 6;
    float4 w0 = __ldg(fw4 + 0), w1 = __ldg(fw4 + 1), w2 = __ldg(fw4 + 2);
    float4 w3 = __ldg(fw4 + 3), w4 = __ldg(fw4 + 4), w5 = __ldg(fw4 + 5);
    float o = __ldg(&fc_b[lane]);
    o += w0.x * mz0 + w0.y * mz1 + w0.z * mz2 + w0.w * mz3;
    o += w1.x * mz4 + w1.y * mz5 + w1.z * mz6 + w1.w * mz7;
    o += w2.x * mx0 + w2.y * mx1 + w2.z * mx2 + w2.w * mx3;
    o += w3.x * mx4 + w3.y * mx5 + w3.z * mx6 + w3.w * mx7;
    o += w4.x * my0 + w4.y * my1 + w4.z * my2 + w4.w * my3;
    o += w5.x * my4 + w5.y * my5 + w5.z * my6 + w5.w * my7;

    int bN = pix >> 12, hw = pix & 4095;
    out[(bN * 32 + lane) * 4096 + hw] = o;
}

// ---------------------------------------------------------------------------
extern "C" void kernel_launch(void* const* d_in, const int* in_sizes, int n_in,
                              void* d_out, int out_size) {
    const float* x      = (const float*)d_in[0];
    const float* conv_w = (const float*)d_in[1];
    const float* conv_b = (const float*)d_in[2];
    const float* u3p    = (const float*)d_in[3];
    const float* cu3p   = (const float*)d_in[4];
    const float* fc_w   = (const float*)d_in[5];
    const float* fc_b   = (const float*)d_in[6];
    float* out = (float*)d_out;

    conv_kernel<<<NPX / 32 + 1, 128>>>(x, conv_w, conv_b, u3p, cu3p);
    sim_kernel<<<NPX / 4, 128>>>(fc_w, fc_b, out);
}